// round 1
// baseline (speedup 1.0000x reference)
#include <cuda_runtime.h>

// Problem constants
#define B_SZ 4096
#define D_SZ 2048
#define E_SZ 16
#define C_SZ 1000

// ---------------- scratch (no allocations allowed) ----------------
__device__ int   g_top_i[B_SZ * 2];
__device__ float g_top_w[B_SZ * 2];
__device__ int   g_cnt[E_SZ];
__device__ int   g_rows[E_SZ * B_SZ];
__device__ float g_rw[E_SZ * B_SZ];

// ---------------- kernel 1: zero output + expert counts ----------------
__global__ void zero_kernel(float* __restrict__ out, int n) {
    int i = blockIdx.x * blockDim.x + threadIdx.x;
    if (i < n) out[i] = 0.0f;
    if (i < E_SZ) g_cnt[i] = 0;
}

// ---------------- kernel 2: gating (x@Wr + br, top-2, softmax) ----------------
// One block (128 threads) per sample row. x row staged in smem;
// 16 lanes-per-group each own one expert, 8 groups stride over D.
__global__ __launch_bounds__(128) void gate_kernel(
    const float* __restrict__ x, const float* __restrict__ Wr,
    const float* __restrict__ br)
{
    const int b   = blockIdx.x;
    const int tid = threadIdx.x;
    const int e   = tid & 15;
    const int g   = tid >> 4;   // 0..7

    __shared__ __align__(16) float xs[D_SZ];
    __shared__ float red[8][16];

    const float* xr = x + (size_t)b * D_SZ;
    // coalesced stage of x row (512 float4)
    for (int i = tid; i < D_SZ / 4; i += 128)
        reinterpret_cast<float4*>(xs)[i] = reinterpret_cast<const float4*>(xr)[i];
    __syncthreads();

    float acc = 0.0f;
    for (int d = g; d < D_SZ; d += 8)
        acc += xs[d] * Wr[d * E_SZ + e];
    red[g][e] = acc;
    __syncthreads();

    if (tid < 16) {
        float s = br[tid];
#pragma unroll
        for (int gg = 0; gg < 8; gg++) s += red[gg][tid];
        red[0][tid] = s;
    }
    __syncthreads();

    if (tid == 0) {
        float best = -1e30f; int bi = 0;
#pragma unroll
        for (int k = 0; k < E_SZ; k++) {
            float v = red[0][k];
            if (v > best) { best = v; bi = k; }
        }
        float sec = -1e30f; int si = 0;
#pragma unroll
        for (int k = 0; k < E_SZ; k++) {
            if (k == bi) continue;
            float v = red[0][k];
            if (v > sec) { sec = v; si = k; }
        }
        float t = expf(sec - best);       // softmax over {best, sec}
        float inv = 1.0f / (1.0f + t);
        g_top_i[b * 2 + 0] = bi;  g_top_w[b * 2 + 0] = inv;
        g_top_i[b * 2 + 1] = si;  g_top_w[b * 2 + 1] = t * inv;
    }
}

// ---------------- kernel 3: bucket assignments by expert ----------------
__global__ void bucket_kernel() {
    int b = blockIdx.x * blockDim.x + threadIdx.x;
    if (b >= B_SZ) return;
#pragma unroll
    for (int k = 0; k < 2; k++) {
        int   e = g_top_i[b * 2 + k];
        float w = g_top_w[b * 2 + k];
        int pos = atomicAdd(&g_cnt[e], 1);
        g_rows[e * B_SZ + pos] = b;
        g_rw[e * B_SZ + pos]   = w;
    }
}

// ---------------- kernel 4: grouped gather-GEMM ----------------
// Per block: 128 gathered rows x 64 output cols, K=2048 in steps of 16.
// Inner product uses packed fma.rn.f32x2 (Blackwell FFMA2): pairs along M
// come free from contiguous smem (As is [k][m]); B values are stored
// duplicated (b,b) so both operands are natural 64-bit lane pairs.
#define FMA_F32X2(d, a, b, c) \
    asm("fma.rn.f32x2 %0, %1, %2, %3;" : "=l"(d) : "l"(a), "l"(b), "l"(c))

__global__ __launch_bounds__(256) void expert_gemm(
    const float* __restrict__ x, const float* __restrict__ We,
    const float* __restrict__ be, float* __restrict__ out)
{
    const int e   = blockIdx.z;
    const int cnt = g_cnt[e];
    const int m0  = blockIdx.y * 128;
    if (m0 >= cnt) return;
    const int n0  = blockIdx.x * 64;

    __shared__ __align__(16) float As[16][128];    // [k][m]
    __shared__ __align__(16) float Bs2[16][128];   // [k][2*c] duplicated pairs
    __shared__ int   rs[128];
    __shared__ float ws[128];

    const int tid = threadIdx.x;

    for (int m = tid; m < 128; m += 256) {
        int gm = m0 + m;
        int r = -1; float w = 0.0f;
        if (gm < cnt) { r = g_rows[e * B_SZ + gm]; w = g_rw[e * B_SZ + gm]; }
        rs[m] = r; ws[m] = w;
    }
    __syncthreads();

    const int tn = tid & 15;   // col group: 16 groups x 4 cols = 64
    const int tm = tid >> 4;   // row group: 16 groups x 8 rows = 128

    // A-load mapping: each thread owns one gathered row half (8 floats)
    const int am = tid >> 1;            // 0..127
    const int ak = (tid & 1) * 8;       // 0 or 8
    int arow = rs[am];
    if (arow < 0) arow = 0;             // garbage lands in discarded rows only
    const float* aptr = x + (size_t)arow * D_SZ + ak;

    // B-load mapping: 16 rows x 16 float4 per k-step
    const int bd  = tid >> 4;           // 0..15 (k within step)
    const int bc4 = (tid & 15) * 4;     // 0..60
    const int bcg = n0 + bc4;
    const bool bvalid = (bcg + 3) < C_SZ;   // C%4==0 -> all-or-nothing
    const float* bptr = We + (size_t)e * D_SZ * C_SZ + (size_t)bd * C_SZ + bcg;

    unsigned long long acc[4][4];
#pragma unroll
    for (int i = 0; i < 4; i++)
#pragma unroll
        for (int j = 0; j < 4; j++) acc[i][j] = 0ull;

    for (int k0 = 0; k0 < D_SZ; k0 += 16) {
        // stage A (transpose into [k][m])
        float4 va0 = *reinterpret_cast<const float4*>(aptr + k0);
        float4 va1 = *reinterpret_cast<const float4*>(aptr + k0 + 4);
        As[ak + 0][am] = va0.x; As[ak + 1][am] = va0.y;
        As[ak + 2][am] = va0.z; As[ak + 3][am] = va0.w;
        As[ak + 4][am] = va1.x; As[ak + 5][am] = va1.y;
        As[ak + 6][am] = va1.z; As[ak + 7][am] = va1.w;
        // stage B duplicated (b,b) pairs
        float4 vb = bvalid ? *reinterpret_cast<const float4*>(bptr + (size_t)k0 * C_SZ)
                           : make_float4(0.f, 0.f, 0.f, 0.f);
        float4 w0 = make_float4(vb.x, vb.x, vb.y, vb.y);
        float4 w1 = make_float4(vb.z, vb.z, vb.w, vb.w);
        *reinterpret_cast<float4*>(&Bs2[bd][bc4 * 2])     = w0;
        *reinterpret_cast<float4*>(&Bs2[bd][bc4 * 2 + 4]) = w1;
        __syncthreads();

#pragma unroll
        for (int k = 0; k < 16; k++) {
            longlong2 a01 = *reinterpret_cast<const longlong2*>(&As[k][tm * 8]);
            longlong2 a23 = *reinterpret_cast<const longlong2*>(&As[k][tm * 8 + 4]);
            longlong2 b01 = *reinterpret_cast<const longlong2*>(&Bs2[k][tn * 8]);
            longlong2 b23 = *reinterpret_cast<const longlong2*>(&Bs2[k][tn * 8 + 4]);
            unsigned long long ap[4] = {
                (unsigned long long)a01.x, (unsigned long long)a01.y,
                (unsigned long long)a23.x, (unsigned long long)a23.y };
            unsigned long long bp[4] = {
                (unsigned long long)b01.x, (unsigned long long)b01.y,
                (unsigned long long)b23.x, (unsigned long long)b23.y };
#pragma unroll
            for (int i = 0; i < 4; i++)
#pragma unroll
                for (int j = 0; j < 4; j++)
                    FMA_F32X2(acc[i][j], ap[i], bp[j], acc[i][j]);
        }
        __syncthreads();
    }

    // epilogue: out[r,c] += w * (acc + be[e,c]); exactly 2 atomic adds per out elem
    const float* bee = be + e * C_SZ;
#pragma unroll
    for (int i = 0; i < 4; i++) {
        const int m_lo = tm * 8 + 2 * i;
        const int r_lo = rs[m_lo], r_hi = rs[m_lo + 1];
        const float w_lo = ws[m_lo], w_hi = ws[m_lo + 1];
#pragma unroll
        for (int j = 0; j < 4; j++) {
            const int c = n0 + tn * 4 + j;
            if (c >= C_SZ) continue;
            float lo = __uint_as_float((unsigned)(acc[i][j] & 0xffffffffull));
            float hi = __uint_as_float((unsigned)(acc[i][j] >> 32));
            float bv = bee[c];
            if (r_lo >= 0) atomicAdd(out + (size_t)r_lo * C_SZ + c, w_lo * (lo + bv));
            if (r_hi >= 0) atomicAdd(out + (size_t)r_hi * C_SZ + c, w_hi * (hi + bv));
        }
    }
}

// ---------------- launch ----------------
extern "C" void kernel_launch(void* const* d_in, const int* in_sizes, int n_in,
                              void* d_out, int out_size) {
    const float* x  = (const float*)d_in[0];   // [4096, 2048]
    const float* Wr = (const float*)d_in[1];   // [2048, 16]
    const float* br = (const float*)d_in[2];   // [16]
    const float* We = (const float*)d_in[3];   // [16, 2048, 1000]
    const float* be = (const float*)d_in[4];   // [16, 1000]
    float* out = (float*)d_out;                // [4096, 1, 1000]

    const int n_out = B_SZ * C_SZ;
    zero_kernel<<<(n_out + 255) / 256, 256>>>(out, n_out);
    gate_kernel<<<B_SZ, 128>>>(x, Wr, br);
    bucket_kernel<<<(B_SZ + 255) / 256, 256>>>();
    dim3 grid((C_SZ + 63) / 64, (B_SZ + 127) / 128, E_SZ);
    expert_gemm<<<grid, 256>>>(x, We, be, out);
}

// round 4
// speedup vs baseline: 3.5726x; 3.5726x over previous
#include <cuda_runtime.h>
#include <cuda_bf16.h>
#include <cstdint>

#define B_SZ 4096
#define D_SZ 2048
#define E_SZ 16
#define C_SZ 1000

#define TM 128
#define TN 128
#define KC 32
#define NCHUNK (D_SZ / KC)      // 64

// smem tile geometry: row = 32 bf16 = 64B, padded to 80B (16B x 5 -> ldmatrix
// phase-conflict-free: (5*r) mod 8 is a permutation of 0..7)
#define ROWB 80
#define TILE_B (128 * ROWB)     // 10240
#define STAGE_B (4 * TILE_B)    // Ah, Al, Bh, Bl = 40960
#define DYN_BYTES (2 * STAGE_B) // 81920

// ---------------- scratch ----------------
__device__ int   g_top_i[B_SZ * 2];
__device__ float g_top_w[B_SZ * 2];
__device__ int   g_cnt[E_SZ];
__device__ int   g_rows[E_SZ * B_SZ];
__device__ float g_rw[E_SZ * B_SZ];

// ---------------- helpers ----------------
__device__ __forceinline__ uint32_t smem_u32(const void* p) {
    uint32_t a;
    asm("{ .reg .u64 t; cvta.to.shared.u64 t, %1; cvt.u32.u64 %0, t; }"
        : "=r"(a) : "l"(p));
    return a;
}
__device__ __forceinline__ void split_pack(float a, float b, uint32_t& h, uint32_t& l) {
    __nv_bfloat162 hh = __floats2bfloat162_rn(a, b);
    float ra = a - __bfloat162float(hh.x);
    float rb = b - __bfloat162float(hh.y);
    __nv_bfloat162 ll = __floats2bfloat162_rn(ra, rb);
    h = *reinterpret_cast<uint32_t*>(&hh);
    l = *reinterpret_cast<uint32_t*>(&ll);
}
__device__ __forceinline__ void sts128(uint32_t addr, uint32_t a, uint32_t b,
                                       uint32_t c, uint32_t d) {
    asm volatile("st.shared.v4.b32 [%0], {%1,%2,%3,%4};"
                 :: "r"(addr), "r"(a), "r"(b), "r"(c), "r"(d) : "memory");
}
#define LDSM4(r, addr)                                                        \
    asm volatile("ldmatrix.sync.aligned.m8n8.x4.shared.b16 {%0,%1,%2,%3}, [%4];" \
                 : "=r"((r)[0]), "=r"((r)[1]), "=r"((r)[2]), "=r"((r)[3])     \
                 : "r"(addr))
#define MMA16816(c, a, b0, b1)                                                \
    asm volatile("mma.sync.aligned.m16n8k16.row.col.f32.bf16.bf16.f32 "       \
                 "{%0,%1,%2,%3}, {%4,%5,%6,%7}, {%8,%9}, {%0,%1,%2,%3};"      \
                 : "+f"((c)[0]), "+f"((c)[1]), "+f"((c)[2]), "+f"((c)[3])     \
                 : "r"((a)[0]), "r"((a)[1]), "r"((a)[2]), "r"((a)[3]),        \
                   "r"(b0), "r"(b1))

// ---------------- kernel 1: zero output + expert counts ----------------
__global__ void zero_kernel(float* __restrict__ out, int n) {
    int i = blockIdx.x * blockDim.x + threadIdx.x;
    if (i < n) out[i] = 0.0f;
    if (i < E_SZ) g_cnt[i] = 0;
}

// ---------------- kernel 2: gating ----------------
__global__ __launch_bounds__(128) void gate_kernel(
    const float* __restrict__ x, const float* __restrict__ Wr,
    const float* __restrict__ br)
{
    const int b   = blockIdx.x;
    const int tid = threadIdx.x;
    const int e   = tid & 15;
    const int g   = tid >> 4;

    __shared__ __align__(16) float xs[D_SZ];
    __shared__ float red[8][16];

    const float* xr = x + (size_t)b * D_SZ;
    for (int i = tid; i < D_SZ / 4; i += 128)
        reinterpret_cast<float4*>(xs)[i] = reinterpret_cast<const float4*>(xr)[i];
    __syncthreads();

    float acc = 0.0f;
    for (int d = g; d < D_SZ; d += 8)
        acc += xs[d] * Wr[d * E_SZ + e];
    red[g][e] = acc;
    __syncthreads();

    if (tid < 16) {
        float s = br[tid];
#pragma unroll
        for (int gg = 0; gg < 8; gg++) s += red[gg][tid];
        red[0][tid] = s;
    }
    __syncthreads();

    if (tid == 0) {
        float best = -1e30f; int bi = 0;
#pragma unroll
        for (int k = 0; k < E_SZ; k++) {
            float v = red[0][k];
            if (v > best) { best = v; bi = k; }
        }
        float sec = -1e30f; int si = 0;
#pragma unroll
        for (int k = 0; k < E_SZ; k++) {
            if (k == bi) continue;
            float v = red[0][k];
            if (v > sec) { sec = v; si = k; }
        }
        float t = expf(sec - best);
        float inv = 1.0f / (1.0f + t);
        g_top_i[b * 2 + 0] = bi;  g_top_w[b * 2 + 0] = inv;
        g_top_i[b * 2 + 1] = si;  g_top_w[b * 2 + 1] = t * inv;
    }
}

// ---------------- kernel 3: bucket by expert ----------------
__global__ void bucket_kernel() {
    int b = blockIdx.x * blockDim.x + threadIdx.x;
    if (b >= B_SZ) return;
#pragma unroll
    for (int k = 0; k < 2; k++) {
        int   e = g_top_i[b * 2 + k];
        float w = g_top_w[b * 2 + k];
        int pos = atomicAdd(&g_cnt[e], 1);
        g_rows[e * B_SZ + pos] = b;
        g_rw[e * B_SZ + pos]   = w;
    }
}

// ---------------- kernel 4: mma.sync grouped gather-GEMM ----------------
extern __shared__ char dynsmem[];

__global__ __launch_bounds__(256, 1) void expert_gemm_mma(
    const float* __restrict__ x, const float* __restrict__ We,
    const float* __restrict__ be, float* __restrict__ out)
{
    const int e   = blockIdx.z;
    const int cnt = g_cnt[e];
    const int m0  = blockIdx.y * TM;
    if (m0 >= cnt) return;
    const int n0  = blockIdx.x * TN;

    __shared__ int   rs[TM];
    __shared__ float ws[TM];
    __shared__ float bes[TN];

    const int tid  = threadIdx.x;
    const int wid  = tid >> 5;
    const int lane = tid & 31;

    const uint32_t sb0 = smem_u32(dynsmem);

    for (int m = tid; m < TM; m += 256) {
        int gm = m0 + m; int r = -1; float w = 0.0f;
        if (gm < cnt) { r = g_rows[e * B_SZ + gm]; w = g_rw[e * B_SZ + gm]; }
        rs[m] = r; ws[m] = w;
    }
    for (int j = tid; j < TN; j += 256) {
        int c = n0 + j;
        bes[j] = (c < C_SZ) ? be[e * C_SZ + c] : 0.0f;
    }
    __syncthreads();

    // ---- staging mappings ----
    // A: 2 threads per gathered row; each owns 16 consecutive k
    const int am = tid >> 1;
    const int ak = (tid & 1) * 16;
    int arow = rs[am]; if (arow < 0) arow = 0;
    const float* __restrict__ xrow = x + (size_t)arow * D_SZ + ak;
    const uint32_t a_sts = (uint32_t)(am * ROWB + (ak >> 4) * 32);
    // B: thread owns column n (0..127) and 16 consecutive k
    const int bn = tid & 127;
    const int bk = (tid >> 7) * 16;
    const bool bval = (n0 + bn) < C_SZ;
    const float* __restrict__ wcol =
        We + (size_t)e * D_SZ * C_SZ + (size_t)bk * C_SZ + (n0 + bn);
    const uint32_t b_sts = (uint32_t)(bn * ROWB + (bk >> 4) * 32);

    float areg[16], breg[16];

    auto ldg_stage = [&](int c) {
        const int k0 = c * KC;
#pragma unroll
        for (int i = 0; i < 4; i++)
            *reinterpret_cast<float4*>(&areg[i * 4]) =
                *reinterpret_cast<const float4*>(xrow + k0 + i * 4);
#pragma unroll
        for (int i = 0; i < 16; i++)
            breg[i] = bval ? wcol[(size_t)(k0 + i) * C_SZ] : 0.0f;
    };
    auto sts_stage = [&](int s) {
        const uint32_t sb = sb0 + (uint32_t)s * STAGE_B;
        uint32_t h[8], l[8];
#pragma unroll
        for (int i = 0; i < 8; i++)
            split_pack(areg[2 * i], areg[2 * i + 1], h[i], l[i]);
        sts128(sb + a_sts,               h[0], h[1], h[2], h[3]);
        sts128(sb + a_sts + 16,          h[4], h[5], h[6], h[7]);
        sts128(sb + TILE_B + a_sts,      l[0], l[1], l[2], l[3]);
        sts128(sb + TILE_B + a_sts + 16, l[4], l[5], l[6], l[7]);
#pragma unroll
        for (int i = 0; i < 8; i++)
            split_pack(breg[2 * i], breg[2 * i + 1], h[i], l[i]);
        sts128(sb + 2 * TILE_B + b_sts,      h[0], h[1], h[2], h[3]);
        sts128(sb + 2 * TILE_B + b_sts + 16, h[4], h[5], h[6], h[7]);
        sts128(sb + 3 * TILE_B + b_sts,      l[0], l[1], l[2], l[3]);
        sts128(sb + 3 * TILE_B + b_sts + 16, l[4], l[5], l[6], l[7]);
    };

    // ---- compute mappings ----
    const int warp_m = (wid >> 2) * 64;    // 0 or 64
    const int warp_n = (wid & 3) * 32;     // 0..96
    // ldmatrix lane addresses (byte offsets into a tile)
    const uint32_t a_lds =
        (uint32_t)((warp_m + (lane & 15)) * ROWB + (lane >> 4) * 16);
    const uint32_t b_lds =
        (uint32_t)((warp_n + ((lane >> 4) & 1) * 8 + (lane & 7)) * ROWB +
                   ((lane >> 3) & 1) * 16);

    float acc[4][4][4];
#pragma unroll
    for (int i = 0; i < 4; i++)
#pragma unroll
        for (int j = 0; j < 4; j++)
#pragma unroll
            for (int q = 0; q < 4; q++) acc[i][j][q] = 0.0f;

    auto compute = [&](int s) {
        const uint32_t sb = sb0 + (uint32_t)s * STAGE_B;
        const uint32_t ah_b = sb + a_lds;
        const uint32_t al_b = sb + TILE_B + a_lds;
        const uint32_t bh_b = sb + 2 * TILE_B + b_lds;
        const uint32_t bl_b = sb + 3 * TILE_B + b_lds;
#pragma unroll
        for (int kk = 0; kk < 2; kk++) {
            uint32_t ah[4][4], al[4][4], bh[2][4], bl[2][4];
#pragma unroll
            for (int mt = 0; mt < 4; mt++) {
                LDSM4(ah[mt], ah_b + mt * 16 * ROWB + kk * 32);
                LDSM4(al[mt], al_b + mt * 16 * ROWB + kk * 32);
            }
#pragma unroll
            for (int np = 0; np < 2; np++) {
                LDSM4(bh[np], bh_b + np * 16 * ROWB + kk * 32);
                LDSM4(bl[np], bl_b + np * 16 * ROWB + kk * 32);
            }
#pragma unroll
            for (int mt = 0; mt < 4; mt++)
#pragma unroll
                for (int nt = 0; nt < 4; nt++) {
                    uint32_t* bhf = &bh[nt >> 1][(nt & 1) * 2];
                    uint32_t* blf = &bl[nt >> 1][(nt & 1) * 2];
                    MMA16816(acc[mt][nt], ah[mt], bhf[0], bhf[1]);
                    MMA16816(acc[mt][nt], ah[mt], blf[0], blf[1]);
                    MMA16816(acc[mt][nt], al[mt], bhf[0], bhf[1]);
                }
        }
    };

    // ---- software-pipelined main loop ----
    ldg_stage(0);
    sts_stage(0);
    __syncthreads();
    for (int c = 0; c < NCHUNK; c++) {
        if (c + 1 < NCHUNK) ldg_stage(c + 1);
        compute(c & 1);
        __syncthreads();
        if (c + 1 < NCHUNK) {
            sts_stage((c + 1) & 1);
            __syncthreads();
        }
    }

    // ---- epilogue: weighted atomic scatter ----
    const int gr = lane >> 2;
    const int gc = (lane & 3) * 2;
#pragma unroll
    for (int mt = 0; mt < 4; mt++) {
#pragma unroll
        for (int half = 0; half < 2; half++) {
            const int m = warp_m + mt * 16 + gr + half * 8;
            const int r = rs[m];
            if (r < 0) continue;
            const float w = ws[m];
            float* orow = out + (size_t)r * C_SZ;
#pragma unroll
            for (int nt = 0; nt < 4; nt++) {
                const int cc = warp_n + nt * 8 + gc;
                const int c = n0 + cc;
                if (c >= C_SZ) continue;
                const float v0 = acc[mt][nt][half * 2 + 0];
                const float v1 = acc[mt][nt][half * 2 + 1];
                atomicAdd(orow + c,     w * (v0 + bes[cc]));
                atomicAdd(orow + c + 1, w * (v1 + bes[cc + 1]));
            }
        }
    }
}

// ---------------- launch ----------------
extern "C" void kernel_launch(void* const* d_in, const int* in_sizes, int n_in,
                              void* d_out, int out_size) {
    const float* x  = (const float*)d_in[0];
    const float* Wr = (const float*)d_in[1];
    const float* br = (const float*)d_in[2];
    const float* We = (const float*)d_in[3];
    const float* be = (const float*)d_in[4];
    float* out = (float*)d_out;

    cudaFuncSetAttribute(expert_gemm_mma,
                         cudaFuncAttributeMaxDynamicSharedMemorySize, DYN_BYTES);

    const int n_out = B_SZ * C_SZ;
    zero_kernel<<<(n_out + 255) / 256, 256>>>(out, n_out);
    gate_kernel<<<B_SZ, 128>>>(x, Wr, br);
    bucket_kernel<<<(B_SZ + 255) / 256, 256>>>();
    dim3 grid((C_SZ + TN - 1) / TN, (B_SZ + TM - 1) / TM, E_SZ);
    expert_gemm_mma<<<grid, 256, DYN_BYTES>>>(x, We, be, out);
}

// round 5
// speedup vs baseline: 3.5870x; 1.0040x over previous
#include <cuda_runtime.h>
#include <cuda_bf16.h>
#include <cstdint>

#define B_SZ 4096
#define D_SZ 2048
#define E_SZ 16
#define C_SZ 1000

#define TM 128
#define TN 128
#define KC 32
#define NCHUNK (D_SZ / KC)      // 64

// smem tile geometry: row = 32 bf16 = 64B, padded to 80B (16B x 5 -> ldmatrix
// phase-conflict-free: (5*r) mod 8 is a permutation of 0..7)
#define ROWB 80
#define TILE_B (128 * ROWB)     // 10240
#define STAGE_B (4 * TILE_B)    // Ah, Al, Bh, Bl = 40960
#define DYN_BYTES (2 * STAGE_B) // 81920

// ---------------- scratch ----------------
__device__ int   g_top_i[B_SZ * 2];
__device__ float g_top_w[B_SZ * 2];
__device__ int   g_cnt[E_SZ];
__device__ int   g_rows[E_SZ * B_SZ];
__device__ float g_rw[E_SZ * B_SZ];

// ---------------- helpers ----------------
__device__ __forceinline__ uint32_t smem_u32(const void* p) {
    uint32_t a;
    asm("{ .reg .u64 t; cvta.to.shared.u64 t, %1; cvt.u32.u64 %0, t; }"
        : "=r"(a) : "l"(p));
    return a;
}
__device__ __forceinline__ void split_pack(float a, float b, uint32_t& h, uint32_t& l) {
    __nv_bfloat162 hh = __floats2bfloat162_rn(a, b);
    float ra = a - __bfloat162float(hh.x);
    float rb = b - __bfloat162float(hh.y);
    __nv_bfloat162 ll = __floats2bfloat162_rn(ra, rb);
    h = *reinterpret_cast<uint32_t*>(&hh);
    l = *reinterpret_cast<uint32_t*>(&ll);
}
__device__ __forceinline__ void sts128(uint32_t addr, uint32_t a, uint32_t b,
                                       uint32_t c, uint32_t d) {
    asm volatile("st.shared.v4.b32 [%0], {%1,%2,%3,%4};"
                 :: "r"(addr), "r"(a), "r"(b), "r"(c), "r"(d) : "memory");
}
#define LDSM4(r, addr)                                                        \
    asm volatile("ldmatrix.sync.aligned.m8n8.x4.shared.b16 {%0,%1,%2,%3}, [%4];" \
                 : "=r"((r)[0]), "=r"((r)[1]), "=r"((r)[2]), "=r"((r)[3])     \
                 : "r"(addr))
#define MMA16816(c, a, b0, b1)                                                \
    asm volatile("mma.sync.aligned.m16n8k16.row.col.f32.bf16.bf16.f32 "       \
                 "{%0,%1,%2,%3}, {%4,%5,%6,%7}, {%8,%9}, {%0,%1,%2,%3};"      \
                 : "+f"((c)[0]), "+f"((c)[1]), "+f"((c)[2]), "+f"((c)[3])     \
                 : "r"((a)[0]), "r"((a)[1]), "r"((a)[2]), "r"((a)[3]),        \
                   "r"(b0), "r"(b1))

// ---------------- kernel 1: zero output + expert counts ----------------
__global__ void zero_kernel(float* __restrict__ out, int n) {
    int i = blockIdx.x * blockDim.x + threadIdx.x;
    if (i < n) out[i] = 0.0f;
    if (i < E_SZ) g_cnt[i] = 0;
}

// ---------------- kernel 2: gating ----------------
__global__ __launch_bounds__(128) void gate_kernel(
    const float* __restrict__ x, const float* __restrict__ Wr,
    const float* __restrict__ br)
{
    const int b   = blockIdx.x;
    const int tid = threadIdx.x;
    const int e   = tid & 15;
    const int g   = tid >> 4;

    __shared__ __align__(16) float xs[D_SZ];
    __shared__ float red[8][16];

    const float* xr = x + (size_t)b * D_SZ;
    for (int i = tid; i < D_SZ / 4; i += 128)
        reinterpret_cast<float4*>(xs)[i] = reinterpret_cast<const float4*>(xr)[i];
    __syncthreads();

    float acc = 0.0f;
    for (int d = g; d < D_SZ; d += 8)
        acc += xs[d] * Wr[d * E_SZ + e];
    red[g][e] = acc;
    __syncthreads();

    if (tid < 16) {
        float s = br[tid];
#pragma unroll
        for (int gg = 0; gg < 8; gg++) s += red[gg][tid];
        red[0][tid] = s;
    }
    __syncthreads();

    if (tid == 0) {
        float best = -1e30f; int bi = 0;
#pragma unroll
        for (int k = 0; k < E_SZ; k++) {
            float v = red[0][k];
            if (v > best) { best = v; bi = k; }
        }
        float sec = -1e30f; int si = 0;
#pragma unroll
        for (int k = 0; k < E_SZ; k++) {
            if (k == bi) continue;
            float v = red[0][k];
            if (v > sec) { sec = v; si = k; }
        }
        float t = expf(sec - best);
        float inv = 1.0f / (1.0f + t);
        g_top_i[b * 2 + 0] = bi;  g_top_w[b * 2 + 0] = inv;
        g_top_i[b * 2 + 1] = si;  g_top_w[b * 2 + 1] = t * inv;
    }
}

// ---------------- kernel 3: bucket by expert ----------------
__global__ void bucket_kernel() {
    int b = blockIdx.x * blockDim.x + threadIdx.x;
    if (b >= B_SZ) return;
#pragma unroll
    for (int k = 0; k < 2; k++) {
        int   e = g_top_i[b * 2 + k];
        float w = g_top_w[b * 2 + k];
        int pos = atomicAdd(&g_cnt[e], 1);
        g_rows[e * B_SZ + pos] = b;
        g_rw[e * B_SZ + pos]   = w;
    }
}

// ---------------- kernel 4: mma.sync grouped gather-GEMM ----------------
extern __shared__ char dynsmem[];

__global__ __launch_bounds__(256, 1) void expert_gemm_mma(
    const float* __restrict__ x, const float* __restrict__ We,
    const float* __restrict__ be, float* __restrict__ out)
{
    const int e   = blockIdx.z;
    const int cnt = g_cnt[e];
    const int m0  = blockIdx.y * TM;
    if (m0 >= cnt) return;
    const int n0  = blockIdx.x * TN;

    __shared__ int   rs[TM];
    __shared__ float ws[TM];
    __shared__ float bes[TN];

    const int tid  = threadIdx.x;
    const int wid  = tid >> 5;
    const int lane = tid & 31;

    const uint32_t sb0 = smem_u32(dynsmem);

    for (int m = tid; m < TM; m += 256) {
        int gm = m0 + m; int r = -1; float w = 0.0f;
        if (gm < cnt) { r = g_rows[e * B_SZ + gm]; w = g_rw[e * B_SZ + gm]; }
        rs[m] = r; ws[m] = w;
    }
    for (int j = tid; j < TN; j += 256) {
        int c = n0 + j;
        bes[j] = (c < C_SZ) ? be[e * C_SZ + c] : 0.0f;
    }
    __syncthreads();

    // ---- staging mappings ----
    // A: 2 threads per gathered row; each owns 16 consecutive k
    const int am = tid >> 1;
    const int ak = (tid & 1) * 16;
    int arow = rs[am]; if (arow < 0) arow = 0;
    const float* __restrict__ xrow = x + (size_t)arow * D_SZ + ak;
    const uint32_t a_sts = (uint32_t)(am * ROWB + (ak >> 4) * 32);
    // B: thread owns column n (0..127) and 16 consecutive k
    const int bn = tid & 127;
    const int bk = (tid >> 7) * 16;
    const bool bval = (n0 + bn) < C_SZ;
    const float* __restrict__ wcol =
        We + (size_t)e * D_SZ * C_SZ + (size_t)bk * C_SZ + (n0 + bn);
    const uint32_t b_sts = (uint32_t)(bn * ROWB + (bk >> 4) * 32);

    float areg[16], breg[16];

    auto ldg_stage = [&](int c) {
        const int k0 = c * KC;
#pragma unroll
        for (int i = 0; i < 4; i++)
            *reinterpret_cast<float4*>(&areg[i * 4]) =
                *reinterpret_cast<const float4*>(xrow + k0 + i * 4);
#pragma unroll
        for (int i = 0; i < 16; i++)
            breg[i] = bval ? wcol[(size_t)(k0 + i) * C_SZ] : 0.0f;
    };
    auto sts_stage = [&](int s) {
        const uint32_t sb = sb0 + (uint32_t)s * STAGE_B;
        uint32_t h[8], l[8];
#pragma unroll
        for (int i = 0; i < 8; i++)
            split_pack(areg[2 * i], areg[2 * i + 1], h[i], l[i]);
        sts128(sb + a_sts,               h[0], h[1], h[2], h[3]);
        sts128(sb + a_sts + 16,          h[4], h[5], h[6], h[7]);
        sts128(sb + TILE_B + a_sts,      l[0], l[1], l[2], l[3]);
        sts128(sb + TILE_B + a_sts + 16, l[4], l[5], l[6], l[7]);
#pragma unroll
        for (int i = 0; i < 8; i++)
            split_pack(breg[2 * i], breg[2 * i + 1], h[i], l[i]);
        sts128(sb + 2 * TILE_B + b_sts,      h[0], h[1], h[2], h[3]);
        sts128(sb + 2 * TILE_B + b_sts + 16, h[4], h[5], h[6], h[7]);
        sts128(sb + 3 * TILE_B + b_sts,      l[0], l[1], l[2], l[3]);
        sts128(sb + 3 * TILE_B + b_sts + 16, l[4], l[5], l[6], l[7]);
    };

    // ---- compute mappings ----
    const int warp_m = (wid >> 2) * 64;    // 0 or 64
    const int warp_n = (wid & 3) * 32;     // 0..96
    // ldmatrix lane addresses (byte offsets into a tile)
    const uint32_t a_lds =
        (uint32_t)((warp_m + (lane & 15)) * ROWB + (lane >> 4) * 16);
    const uint32_t b_lds =
        (uint32_t)((warp_n + ((lane >> 4) & 1) * 8 + (lane & 7)) * ROWB +
                   ((lane >> 3) & 1) * 16);

    float acc[4][4][4];
#pragma unroll
    for (int i = 0; i < 4; i++)
#pragma unroll
        for (int j = 0; j < 4; j++)
#pragma unroll
            for (int q = 0; q < 4; q++) acc[i][j][q] = 0.0f;

    auto compute = [&](int s) {
        const uint32_t sb = sb0 + (uint32_t)s * STAGE_B;
        const uint32_t ah_b = sb + a_lds;
        const uint32_t al_b = sb + TILE_B + a_lds;
        const uint32_t bh_b = sb + 2 * TILE_B + b_lds;
        const uint32_t bl_b = sb + 3 * TILE_B + b_lds;
#pragma unroll
        for (int kk = 0; kk < 2; kk++) {
            uint32_t ah[4][4], al[4][4], bh[2][4], bl[2][4];
#pragma unroll
            for (int mt = 0; mt < 4; mt++) {
                LDSM4(ah[mt], ah_b + mt * 16 * ROWB + kk * 32);
                LDSM4(al[mt], al_b + mt * 16 * ROWB + kk * 32);
            }
#pragma unroll
            for (int np = 0; np < 2; np++) {
                LDSM4(bh[np], bh_b + np * 16 * ROWB + kk * 32);
                LDSM4(bl[np], bl_b + np * 16 * ROWB + kk * 32);
            }
#pragma unroll
            for (int mt = 0; mt < 4; mt++)
#pragma unroll
                for (int nt = 0; nt < 4; nt++) {
                    uint32_t* bhf = &bh[nt >> 1][(nt & 1) * 2];
                    uint32_t* blf = &bl[nt >> 1][(nt & 1) * 2];
                    MMA16816(acc[mt][nt], ah[mt], bhf[0], bhf[1]);
                    MMA16816(acc[mt][nt], ah[mt], blf[0], blf[1]);
                    MMA16816(acc[mt][nt], al[mt], bhf[0], bhf[1]);
                }
        }
    };

    // ---- software-pipelined main loop ----
    ldg_stage(0);
    sts_stage(0);
    __syncthreads();
    for (int c = 0; c < NCHUNK; c++) {
        if (c + 1 < NCHUNK) ldg_stage(c + 1);
        compute(c & 1);
        __syncthreads();
        if (c + 1 < NCHUNK) {
            sts_stage((c + 1) & 1);
            __syncthreads();
        }
    }

    // ---- epilogue: weighted atomic scatter ----
    const int gr = lane >> 2;
    const int gc = (lane & 3) * 2;
#pragma unroll
    for (int mt = 0; mt < 4; mt++) {
#pragma unroll
        for (int half = 0; half < 2; half++) {
            const int m = warp_m + mt * 16 + gr + half * 8;
            const int r = rs[m];
            if (r < 0) continue;
            const float w = ws[m];
            float* orow = out + (size_t)r * C_SZ;
#pragma unroll
            for (int nt = 0; nt < 4; nt++) {
                const int cc = warp_n + nt * 8 + gc;
                const int c = n0 + cc;
                if (c >= C_SZ) continue;
                const float v0 = acc[mt][nt][half * 2 + 0];
                const float v1 = acc[mt][nt][half * 2 + 1];
                atomicAdd(orow + c,     w * (v0 + bes[cc]));
                atomicAdd(orow + c + 1, w * (v1 + bes[cc + 1]));
            }
        }
    }
}

// ---------------- launch ----------------
extern "C" void kernel_launch(void* const* d_in, const int* in_sizes, int n_in,
                              void* d_out, int out_size) {
    const float* x  = (const float*)d_in[0];
    const float* Wr = (const float*)d_in[1];
    const float* br = (const float*)d_in[2];
    const float* We = (const float*)d_in[3];
    const float* be = (const float*)d_in[4];
    float* out = (float*)d_out;

    cudaFuncSetAttribute(expert_gemm_mma,
                         cudaFuncAttributeMaxDynamicSharedMemorySize, DYN_BYTES);

    const int n_out = B_SZ * C_SZ;
    zero_kernel<<<(n_out + 255) / 256, 256>>>(out, n_out);
    gate_kernel<<<B_SZ, 128>>>(x, Wr, br);
    bucket_kernel<<<(B_SZ + 255) / 256, 256>>>();
    dim3 grid((C_SZ + TN - 1) / TN, (B_SZ + TM - 1) / TM, E_SZ);
    expert_gemm_mma<<<grid, 256, DYN_BYTES>>>(x, We, be, out);
}

// round 7
// speedup vs baseline: 3.7245x; 1.0383x over previous
#include <cuda_runtime.h>
#include <cuda_bf16.h>
#include <cstdint>

#define B_SZ 4096
#define D_SZ 2048
#define E_SZ 16
#define C_SZ 1000

#define TM 128
#define TN 128
#define KC 32
#define NCHUNK (D_SZ / KC)      // 64

// smem tile geometry: row = 32 bf16 = 64B, padded to 80B (16B x 5 -> ldmatrix
// phase-conflict-free: (5*r) mod 8 is a permutation of 0..7)
#define ROWB 80
#define TILE_B (128 * ROWB)     // 10240
#define STAGE_B (4 * TILE_B)    // Ah, Al, Bh, Bl = 40960
#define DYN_BYTES (2 * STAGE_B) // 81920

// ---------------- scratch ----------------
__device__ int   g_cnt[E_SZ];
__device__ int   g_rows[E_SZ * B_SZ];
__device__ float g_rw[E_SZ * B_SZ];

// ---------------- helpers ----------------
__device__ __forceinline__ uint32_t smem_u32(const void* p) {
    uint32_t a;
    asm("{ .reg .u64 t; cvta.to.shared.u64 t, %1; cvt.u32.u64 %0, t; }"
        : "=r"(a) : "l"(p));
    return a;
}
__device__ __forceinline__ void split_pack(float a, float b, uint32_t& h, uint32_t& l) {
    __nv_bfloat162 hh = __floats2bfloat162_rn(a, b);
    float ra = a - __bfloat162float(hh.x);
    float rb = b - __bfloat162float(hh.y);
    __nv_bfloat162 ll = __floats2bfloat162_rn(ra, rb);
    h = *reinterpret_cast<uint32_t*>(&hh);
    l = *reinterpret_cast<uint32_t*>(&ll);
}
__device__ __forceinline__ void sts128(uint32_t addr, uint32_t a, uint32_t b,
                                       uint32_t c, uint32_t d) {
    asm volatile("st.shared.v4.b32 [%0], {%1,%2,%3,%4};"
                 :: "r"(addr), "r"(a), "r"(b), "r"(c), "r"(d) : "memory");
}
#define LDSM4(r, addr)                                                        \
    asm volatile("ldmatrix.sync.aligned.m8n8.x4.shared.b16 {%0,%1,%2,%3}, [%4];" \
                 : "=r"((r)[0]), "=r"((r)[1]), "=r"((r)[2]), "=r"((r)[3])     \
                 : "r"(addr))
#define MMA16816(c, a, b0, b1)                                                \
    asm volatile("mma.sync.aligned.m16n8k16.row.col.f32.bf16.bf16.f32 "       \
                 "{%0,%1,%2,%3}, {%4,%5,%6,%7}, {%8,%9}, {%0,%1,%2,%3};"      \
                 : "+f"((c)[0]), "+f"((c)[1]), "+f"((c)[2]), "+f"((c)[3])     \
                 : "r"((a)[0]), "r"((a)[1]), "r"((a)[2]), "r"((a)[3]),        \
                   "r"(b0), "r"(b1))

// ---------------- kernel 1: zero output + expert counts ----------------
__global__ void zero_kernel(float* __restrict__ out, int n) {
    int i = blockIdx.x * blockDim.x + threadIdx.x;
    if (i < n) out[i] = 0.0f;
    if (i < E_SZ) g_cnt[i] = 0;
}

// ---------------- kernel 2: fused gating + top-2 softmax + bucket ----------
// 128 blocks x 32 rows. Wr is chunk-staged in smem ONCE per block (previous
// version re-read 128KB of Wr from L2 per ROW-block: 512MB of L2 traffic).
#define GR 32
__global__ __launch_bounds__(256) void gate_fused(
    const float* __restrict__ x, const float* __restrict__ Wr,
    const float* __restrict__ br)
{
    __shared__ __align__(16) float xs[GR][132];    // pad 132: conflict-free
    __shared__ __align__(16) float wrs[E_SZ][132]; // transposed [e][d]
    __shared__ float lg[GR][17];

    const int tid  = threadIdx.x;
    const int row0 = blockIdx.x * GR;
    const int e    = tid & 15;
    const int g    = tid >> 4;      // 0..15, owns rows 2g, 2g+1

    float acc0 = 0.0f, acc1 = 0.0f;

    for (int ch = 0; ch < D_SZ / 128; ch++) {
        const int d0 = ch * 128;
        // stage x rows: GR x 128 floats
        for (int i = tid; i < GR * 32; i += 256) {
            int rr = i >> 5, d4 = (i & 31) * 4;
            *reinterpret_cast<float4*>(&xs[rr][d4]) =
                *reinterpret_cast<const float4*>(
                    x + (size_t)(row0 + rr) * D_SZ + d0 + d4);
        }
        // stage Wr chunk transposed: 128 d x 16 e
        for (int i = tid; i < 128 * 4; i += 256) {
            int d = i >> 2, e4 = (i & 3) * 4;
            float4 v = *reinterpret_cast<const float4*>(
                Wr + (size_t)(d0 + d) * E_SZ + e4);
            wrs[e4 + 0][d] = v.x; wrs[e4 + 1][d] = v.y;
            wrs[e4 + 2][d] = v.z; wrs[e4 + 3][d] = v.w;
        }
        __syncthreads();
#pragma unroll 8
        for (int d = 0; d < 128; d += 4) {
            float4 w4 = *reinterpret_cast<const float4*>(&wrs[e][d]);
            float4 x0 = *reinterpret_cast<const float4*>(&xs[2 * g][d]);
            float4 x1 = *reinterpret_cast<const float4*>(&xs[2 * g + 1][d]);
            acc0 += x0.x * w4.x + x0.y * w4.y + x0.z * w4.z + x0.w * w4.w;
            acc1 += x1.x * w4.x + x1.y * w4.y + x1.z * w4.z + x1.w * w4.w;
        }
        __syncthreads();
    }
    lg[2 * g][e]     = acc0 + br[e];
    lg[2 * g + 1][e] = acc1 + br[e];
    __syncthreads();

    if (tid < GR) {
        const int r = row0 + tid;
        float best = -1e30f; int bi = 0;
#pragma unroll
        for (int k = 0; k < E_SZ; k++) {
            float v = lg[tid][k];
            if (v > best) { best = v; bi = k; }
        }
        float sec = -1e30f; int si = 0;
#pragma unroll
        for (int k = 0; k < E_SZ; k++) {
            if (k == bi) continue;
            float v = lg[tid][k];
            if (v > sec) { sec = v; si = k; }
        }
        float t   = expf(sec - best);
        float inv = 1.0f / (1.0f + t);
        int p0 = atomicAdd(&g_cnt[bi], 1);
        g_rows[bi * B_SZ + p0] = r;  g_rw[bi * B_SZ + p0] = inv;
        int p1 = atomicAdd(&g_cnt[si], 1);
        g_rows[si * B_SZ + p1] = r;  g_rw[si * B_SZ + p1] = t * inv;
    }
}

// ---------------- kernel 3: mma.sync grouped gather-GEMM ----------------
extern __shared__ char dynsmem[];

__global__ __launch_bounds__(256, 1) void expert_gemm_mma(
    const float* __restrict__ x, const float* __restrict__ We,
    const float* __restrict__ be, float* __restrict__ out)
{
    const int e   = blockIdx.z;
    const int cnt = g_cnt[e];
    const int m0  = blockIdx.y * TM;
    if (m0 >= cnt) return;
    const int n0  = blockIdx.x * TN;

    __shared__ int   rs[TM];
    __shared__ float ws[TM];
    __shared__ float bes[TN];

    const int tid  = threadIdx.x;
    const int wid  = tid >> 5;
    const int lane = tid & 31;

    const uint32_t sb0 = smem_u32(dynsmem);

    for (int m = tid; m < TM; m += 256) {
        int gm = m0 + m; int r = -1; float w = 0.0f;
        if (gm < cnt) { r = g_rows[e * B_SZ + gm]; w = g_rw[e * B_SZ + gm]; }
        rs[m] = r; ws[m] = w;
    }
    for (int j = tid; j < TN; j += 256) {
        int c = n0 + j;
        bes[j] = (c < C_SZ) ? be[e * C_SZ + c] : 0.0f;
    }
    __syncthreads();

    // ---- staging mappings ----
    const int am = tid >> 1;
    const int ak = (tid & 1) * 16;
    int arow = rs[am]; if (arow < 0) arow = 0;
    const float* __restrict__ xrow = x + (size_t)arow * D_SZ + ak;
    const uint32_t a_sts = (uint32_t)(am * ROWB + (ak >> 4) * 32);
    const int bn = tid & 127;
    const int bk = (tid >> 7) * 16;
    const bool bval = (n0 + bn) < C_SZ;
    const float* __restrict__ wcol =
        We + (size_t)e * D_SZ * C_SZ + (size_t)bk * C_SZ + (n0 + bn);
    const uint32_t b_sts = (uint32_t)(bn * ROWB + (bk >> 4) * 32);

    float areg[16], breg[16];

    auto ldg_stage = [&](int c) {
        const int k0 = c * KC;
#pragma unroll
        for (int i = 0; i < 4; i++)
            *reinterpret_cast<float4*>(&areg[i * 4]) =
                *reinterpret_cast<const float4*>(xrow + k0 + i * 4);
#pragma unroll
        for (int i = 0; i < 16; i++)
            breg[i] = bval ? wcol[(size_t)(k0 + i) * C_SZ] : 0.0f;
    };
    auto sts_stage = [&](int s) {
        const uint32_t sb = sb0 + (uint32_t)s * STAGE_B;
        uint32_t h[8], l[8];
#pragma unroll
        for (int i = 0; i < 8; i++)
            split_pack(areg[2 * i], areg[2 * i + 1], h[i], l[i]);
        sts128(sb + a_sts,               h[0], h[1], h[2], h[3]);
        sts128(sb + a_sts + 16,          h[4], h[5], h[6], h[7]);
        sts128(sb + TILE_B + a_sts,      l[0], l[1], l[2], l[3]);
        sts128(sb + TILE_B + a_sts + 16, l[4], l[5], l[6], l[7]);
#pragma unroll
        for (int i = 0; i < 8; i++)
            split_pack(breg[2 * i], breg[2 * i + 1], h[i], l[i]);
        sts128(sb + 2 * TILE_B + b_sts,      h[0], h[1], h[2], h[3]);
        sts128(sb + 2 * TILE_B + b_sts + 16, h[4], h[5], h[6], h[7]);
        sts128(sb + 3 * TILE_B + b_sts,      l[0], l[1], l[2], l[3]);
        sts128(sb + 3 * TILE_B + b_sts + 16, l[4], l[5], l[6], l[7]);
    };

    // ---- compute mappings ----
    const int warp_m = (wid >> 2) * 64;
    const int warp_n = (wid & 3) * 32;
    const uint32_t a_lds =
        (uint32_t)((warp_m + (lane & 15)) * ROWB + (lane >> 4) * 16);
    const uint32_t b_lds =
        (uint32_t)((warp_n + ((lane >> 4) & 1) * 8 + (lane & 7)) * ROWB +
                   ((lane >> 3) & 1) * 16);

    float acc[4][4][4];
#pragma unroll
    for (int i = 0; i < 4; i++)
#pragma unroll
        for (int j = 0; j < 4; j++)
#pragma unroll
            for (int q = 0; q < 4; q++) acc[i][j][q] = 0.0f;

    auto compute = [&](int s) {
        const uint32_t sb = sb0 + (uint32_t)s * STAGE_B;
        const uint32_t ah_b = sb + a_lds;
        const uint32_t al_b = sb + TILE_B + a_lds;
        const uint32_t bh_b = sb + 2 * TILE_B + b_lds;
        const uint32_t bl_b = sb + 3 * TILE_B + b_lds;
#pragma unroll
        for (int kk = 0; kk < 2; kk++) {
            uint32_t ah[4][4], al[4][4], bh[2][4], bl[2][4];
#pragma unroll
            for (int mt = 0; mt < 4; mt++) {
                LDSM4(ah[mt], ah_b + mt * 16 * ROWB + kk * 32);
                LDSM4(al[mt], al_b + mt * 16 * ROWB + kk * 32);
            }
#pragma unroll
            for (int np = 0; np < 2; np++) {
                LDSM4(bh[np], bh_b + np * 16 * ROWB + kk * 32);
                LDSM4(bl[np], bl_b + np * 16 * ROWB + kk * 32);
            }
#pragma unroll
            for (int mt = 0; mt < 4; mt++)
#pragma unroll
                for (int nt = 0; nt < 4; nt++) {
                    uint32_t* bhf = &bh[nt >> 1][(nt & 1) * 2];
                    uint32_t* blf = &bl[nt >> 1][(nt & 1) * 2];
                    MMA16816(acc[mt][nt], ah[mt], bhf[0], bhf[1]);
                    MMA16816(acc[mt][nt], ah[mt], blf[0], blf[1]);
                    MMA16816(acc[mt][nt], al[mt], bhf[0], bhf[1]);
                }
        }
    };

    // ---- main loop: ONE barrier per chunk ----
    // sts(c+1) writes the buffer opposite to compute(c)'s reads, and the
    // previous reader of that buffer (compute(c-1)) is fenced by the prior
    // iteration's end-of-loop barrier -> the mid-chunk barrier is dead.
    ldg_stage(0);
    sts_stage(0);
    __syncthreads();
    for (int c = 0; c < NCHUNK; c++) {
        if (c + 1 < NCHUNK) ldg_stage(c + 1);
        compute(c & 1);
        if (c + 1 < NCHUNK) sts_stage((c + 1) & 1);
        __syncthreads();
    }

    // ---- epilogue: weighted atomic scatter ----
    const int gr = lane >> 2;
    const int gc = (lane & 3) * 2;
#pragma unroll
    for (int mt = 0; mt < 4; mt++) {
#pragma unroll
        for (int half = 0; half < 2; half++) {
            const int m = warp_m + mt * 16 + gr + half * 8;
            const int r = rs[m];
            if (r < 0) continue;
            const float w = ws[m];
            float* orow = out + (size_t)r * C_SZ;
#pragma unroll
            for (int nt = 0; nt < 4; nt++) {
                const int cc = warp_n + nt * 8 + gc;
                const int c = n0 + cc;
                if (c >= C_SZ) continue;
                const float v0 = acc[mt][nt][half * 2 + 0];
                const float v1 = acc[mt][nt][half * 2 + 1];
                atomicAdd(orow + c,     w * (v0 + bes[cc]));
                atomicAdd(orow + c + 1, w * (v1 + bes[cc + 1]));
            }
        }
    }
}

// ---------------- launch ----------------
extern "C" void kernel_launch(void* const* d_in, const int* in_sizes, int n_in,
                              void* d_out, int out_size) {
    const float* x  = (const float*)d_in[0];
    const float* Wr = (const float*)d_in[1];
    const float* br = (const float*)d_in[2];
    const float* We = (const float*)d_in[3];
    const float* be = (const float*)d_in[4];
    float* out = (float*)d_out;

    cudaFuncSetAttribute(expert_gemm_mma,
                         cudaFuncAttributeMaxDynamicSharedMemorySize, DYN_BYTES);

    const int n_out = B_SZ * C_SZ;
    zero_kernel<<<(n_out + 255) / 256, 256>>>(out, n_out);
    gate_fused<<<B_SZ / GR, 256>>>(x, Wr, br);
    dim3 grid((C_SZ + TN - 1) / TN, (B_SZ + TM - 1) / TM, E_SZ);
    expert_gemm_mma<<<grid, 256, DYN_BYTES>>>(x, We, be, out);
}

// round 8
// speedup vs baseline: 3.7483x; 1.0064x over previous
#include <cuda_runtime.h>
#include <cuda_bf16.h>
#include <cstdint>

#define B_SZ 4096
#define D_SZ 2048
#define E_SZ 16
#define C_SZ 1000

#define TM 128
#define TN 256
#define KC 32
#define NCHUNK (D_SZ / KC)      // 64

// smem row = 32 bf16 = 64B, padded to 80B (5x16B -> ldmatrix conflict-free)
#define ROWB 80
#define A_TILE_B (128 * ROWB)   // 10240
#define B_TILE_B (256 * ROWB)   // 20480
#define OFF_AH 0
#define OFF_AL A_TILE_B
#define OFF_BH (2 * A_TILE_B)
#define OFF_BL (2 * A_TILE_B + B_TILE_B)
#define STAGE_B (2 * A_TILE_B + 2 * B_TILE_B)   // 61440
#define DYN_BYTES (2 * STAGE_B)                 // 122880

// ---------------- scratch ----------------
__device__ int   g_cnt[E_SZ];
__device__ int   g_rows[E_SZ * B_SZ];
__device__ float g_rw[E_SZ * B_SZ];

// ---------------- helpers ----------------
__device__ __forceinline__ uint32_t smem_u32(const void* p) {
    uint32_t a;
    asm("{ .reg .u64 t; cvta.to.shared.u64 t, %1; cvt.u32.u64 %0, t; }"
        : "=r"(a) : "l"(p));
    return a;
}
__device__ __forceinline__ void split_pack(float a, float b, uint32_t& h, uint32_t& l) {
    __nv_bfloat162 hh = __floats2bfloat162_rn(a, b);
    float ra = a - __bfloat162float(hh.x);
    float rb = b - __bfloat162float(hh.y);
    __nv_bfloat162 ll = __floats2bfloat162_rn(ra, rb);
    h = *reinterpret_cast<uint32_t*>(&hh);
    l = *reinterpret_cast<uint32_t*>(&ll);
}
__device__ __forceinline__ void sts128(uint32_t addr, uint32_t a, uint32_t b,
                                       uint32_t c, uint32_t d) {
    asm volatile("st.shared.v4.b32 [%0], {%1,%2,%3,%4};"
                 :: "r"(addr), "r"(a), "r"(b), "r"(c), "r"(d) : "memory");
}
#define LDSM4(r, addr)                                                        \
    asm volatile("ldmatrix.sync.aligned.m8n8.x4.shared.b16 {%0,%1,%2,%3}, [%4];" \
                 : "=r"((r)[0]), "=r"((r)[1]), "=r"((r)[2]), "=r"((r)[3])     \
                 : "r"(addr))
#define MMA16816(c, a, b0, b1)                                                \
    asm volatile("mma.sync.aligned.m16n8k16.row.col.f32.bf16.bf16.f32 "       \
                 "{%0,%1,%2,%3}, {%4,%5,%6,%7}, {%8,%9}, {%0,%1,%2,%3};"      \
                 : "+f"((c)[0]), "+f"((c)[1]), "+f"((c)[2]), "+f"((c)[3])     \
                 : "r"((a)[0]), "r"((a)[1]), "r"((a)[2]), "r"((a)[3]),        \
                   "r"(b0), "r"(b1))

// ---------------- kernel 1: zero output + expert counts (vectorized) -------
__global__ void zero_kernel(float4* __restrict__ out, int n4) {
    int i = blockIdx.x * blockDim.x + threadIdx.x;
    if (i < n4) out[i] = make_float4(0.f, 0.f, 0.f, 0.f);
    if (i < E_SZ) g_cnt[i] = 0;
}

// ---------------- kernel 2: fused gating + top-2 softmax + bucket ----------
#define GR 32
__global__ __launch_bounds__(256) void gate_fused(
    const float* __restrict__ x, const float* __restrict__ Wr,
    const float* __restrict__ br)
{
    __shared__ __align__(16) float xs[GR][132];
    __shared__ __align__(16) float wrs[E_SZ][132];
    __shared__ float lg[GR][17];

    const int tid  = threadIdx.x;
    const int row0 = blockIdx.x * GR;
    const int e    = tid & 15;
    const int g    = tid >> 4;

    float acc0 = 0.0f, acc1 = 0.0f;

    for (int ch = 0; ch < D_SZ / 128; ch++) {
        const int d0 = ch * 128;
        for (int i = tid; i < GR * 32; i += 256) {
            int rr = i >> 5, d4 = (i & 31) * 4;
            *reinterpret_cast<float4*>(&xs[rr][d4]) =
                *reinterpret_cast<const float4*>(
                    x + (size_t)(row0 + rr) * D_SZ + d0 + d4);
        }
        for (int i = tid; i < 128 * 4; i += 256) {
            int d = i >> 2, e4 = (i & 3) * 4;
            float4 v = *reinterpret_cast<const float4*>(
                Wr + (size_t)(d0 + d) * E_SZ + e4);
            wrs[e4 + 0][d] = v.x; wrs[e4 + 1][d] = v.y;
            wrs[e4 + 2][d] = v.z; wrs[e4 + 3][d] = v.w;
        }
        __syncthreads();
#pragma unroll 8
        for (int d = 0; d < 128; d += 4) {
            float4 w4 = *reinterpret_cast<const float4*>(&wrs[e][d]);
            float4 x0 = *reinterpret_cast<const float4*>(&xs[2 * g][d]);
            float4 x1 = *reinterpret_cast<const float4*>(&xs[2 * g + 1][d]);
            acc0 += x0.x * w4.x + x0.y * w4.y + x0.z * w4.z + x0.w * w4.w;
            acc1 += x1.x * w4.x + x1.y * w4.y + x1.z * w4.z + x1.w * w4.w;
        }
        __syncthreads();
    }
    lg[2 * g][e]     = acc0 + br[e];
    lg[2 * g + 1][e] = acc1 + br[e];
    __syncthreads();

    if (tid < GR) {
        const int r = row0 + tid;
        float best = -1e30f; int bi = 0;
#pragma unroll
        for (int k = 0; k < E_SZ; k++) {
            float v = lg[tid][k];
            if (v > best) { best = v; bi = k; }
        }
        float sec = -1e30f; int si = 0;
#pragma unroll
        for (int k = 0; k < E_SZ; k++) {
            if (k == bi) continue;
            float v = lg[tid][k];
            if (v > sec) { sec = v; si = k; }
        }
        float t   = expf(sec - best);
        float inv = 1.0f / (1.0f + t);
        int p0 = atomicAdd(&g_cnt[bi], 1);
        g_rows[bi * B_SZ + p0] = r;  g_rw[bi * B_SZ + p0] = inv;
        int p1 = atomicAdd(&g_cnt[si], 1);
        g_rows[si * B_SZ + p1] = r;  g_rw[si * B_SZ + p1] = t * inv;
    }
}

// ---------------- kernel 3: mma.sync grouped gather-GEMM (128x256) ---------
extern __shared__ char dynsmem[];

__global__ __launch_bounds__(256, 1) void expert_gemm_mma(
    const float* __restrict__ x, const float* __restrict__ We,
    const float* __restrict__ be, float* __restrict__ out)
{
    const int e   = blockIdx.z;
    const int cnt = g_cnt[e];
    const int m0  = blockIdx.y * TM;
    if (m0 >= cnt) return;
    const int n0  = blockIdx.x * TN;

    __shared__ int   rs[TM];
    __shared__ float ws[TM];
    __shared__ float bes[TN];

    const int tid  = threadIdx.x;
    const int wid  = tid >> 5;
    const int lane = tid & 31;

    const uint32_t sb0 = smem_u32(dynsmem);

    for (int m = tid; m < TM; m += 256) {
        int gm = m0 + m; int r = -1; float w = 0.0f;
        if (gm < cnt) { r = g_rows[e * B_SZ + gm]; w = g_rw[e * B_SZ + gm]; }
        rs[m] = r; ws[m] = w;
    }
    for (int j = tid; j < TN; j += 256) {
        int c = n0 + j;
        bes[j] = (c < C_SZ) ? be[e * C_SZ + c] : 0.0f;
    }
    __syncthreads();

    // ---- staging mappings ----
    // A: 2 threads per gathered row, 16 consecutive k each
    const int am = tid >> 1;
    const int ak = (tid & 1) * 16;
    int arow = rs[am]; if (arow < 0) arow = 0;
    const float* __restrict__ xrow = x + (size_t)arow * D_SZ + ak;
    const uint32_t a_sts = (uint32_t)(am * ROWB + (ak >> 4) * 32);
    // B: 1 thread per output col, 32 k values
    const int bn = tid;                 // 0..255
    const bool bval = (n0 + bn) < C_SZ;
    const float* __restrict__ wcol =
        We + (size_t)e * D_SZ * C_SZ + (n0 + bn);
    const uint32_t b_sts = (uint32_t)(bn * ROWB);

    float areg[16], breg[32];

    auto ldg_a = [&](int c) {
        const int k0 = c * KC;
#pragma unroll
        for (int i = 0; i < 4; i++)
            *reinterpret_cast<float4*>(&areg[i * 4]) =
                *reinterpret_cast<const float4*>(xrow + k0 + i * 4);
    };
    auto ldg_b = [&](int c) {
        const int k0 = c * KC;
#pragma unroll
        for (int i = 0; i < 32; i++)
            breg[i] = bval ? wcol[(size_t)(k0 + i) * C_SZ] : 0.0f;
    };
    auto sts_a = [&](int s) {
        const uint32_t sb = sb0 + (uint32_t)s * STAGE_B;
        uint32_t h[8], l[8];
#pragma unroll
        for (int i = 0; i < 8; i++)
            split_pack(areg[2 * i], areg[2 * i + 1], h[i], l[i]);
        sts128(sb + OFF_AH + a_sts,      h[0], h[1], h[2], h[3]);
        sts128(sb + OFF_AH + a_sts + 16, h[4], h[5], h[6], h[7]);
        sts128(sb + OFF_AL + a_sts,      l[0], l[1], l[2], l[3]);
        sts128(sb + OFF_AL + a_sts + 16, l[4], l[5], l[6], l[7]);
    };
    auto sts_b = [&](int s) {
        const uint32_t sb = sb0 + (uint32_t)s * STAGE_B;
        uint32_t h[16], l[16];
#pragma unroll
        for (int i = 0; i < 16; i++)
            split_pack(breg[2 * i], breg[2 * i + 1], h[i], l[i]);
#pragma unroll
        for (int q = 0; q < 4; q++) {
            sts128(sb + OFF_BH + b_sts + q * 16,
                   h[4 * q], h[4 * q + 1], h[4 * q + 2], h[4 * q + 3]);
            sts128(sb + OFF_BL + b_sts + q * 16,
                   l[4 * q], l[4 * q + 1], l[4 * q + 2], l[4 * q + 3]);
        }
    };

    // ---- compute mappings: 2x4 warp grid, 64x64 warp tiles ----
    const int warp_m = (wid & 1) * 64;     // 0 or 64
    const int warp_n = (wid >> 1) * 64;    // 0, 64, 128, 192
    const uint32_t a_lds =
        (uint32_t)((warp_m + (lane & 15)) * ROWB + (lane >> 4) * 16);
    const uint32_t b_lds =
        (uint32_t)((warp_n + ((lane >> 4) & 1) * 8 + (lane & 7)) * ROWB +
                   ((lane >> 3) & 1) * 16);

    float acc[4][8][4];
#pragma unroll
    for (int i = 0; i < 4; i++)
#pragma unroll
        for (int j = 0; j < 8; j++)
#pragma unroll
            for (int q = 0; q < 4; q++) acc[i][j][q] = 0.0f;

    auto compute_kk = [&](int s, int kk) {
        const uint32_t sb = sb0 + (uint32_t)s * STAGE_B;
        const uint32_t koff = (uint32_t)(kk * 32);
        uint32_t ah[4][4], al[4][4];
#pragma unroll
        for (int mt = 0; mt < 4; mt++) {
            LDSM4(ah[mt], sb + OFF_AH + a_lds + mt * (16 * ROWB) + koff);
            LDSM4(al[mt], sb + OFF_AL + a_lds + mt * (16 * ROWB) + koff);
        }
#pragma unroll
        for (int nh = 0; nh < 2; nh++) {
            uint32_t bh[2][4], bl[2][4];
#pragma unroll
            for (int np = 0; np < 2; np++) {
                const uint32_t ro = (uint32_t)((nh * 2 + np) * (16 * ROWB)) + koff;
                LDSM4(bh[np], sb + OFF_BH + b_lds + ro);
                LDSM4(bl[np], sb + OFF_BL + b_lds + ro);
            }
#pragma unroll
            for (int mt = 0; mt < 4; mt++)
#pragma unroll
                for (int nt2 = 0; nt2 < 4; nt2++) {
                    float* a4 = acc[mt][nh * 4 + nt2];
                    uint32_t* bhf = &bh[nt2 >> 1][(nt2 & 1) * 2];
                    uint32_t* blf = &bl[nt2 >> 1][(nt2 & 1) * 2];
                    MMA16816(a4, ah[mt], bhf[0], bhf[1]);
                    MMA16816(a4, ah[mt], blf[0], blf[1]);
                    MMA16816(a4, al[mt], bhf[0], bhf[1]);
                }
        }
    };

    // ---- main loop: staging interleaved into compute shadow ----
    ldg_a(0); ldg_b(0);
    sts_a(0); sts_b(0);
    __syncthreads();
    for (int c = 0; c < NCHUNK; c++) {
        const int s = c & 1;
        const bool more = (c + 1 < NCHUNK);
        if (more) ldg_a(c + 1);
        compute_kk(s, 0);
        if (more) { sts_a(s ^ 1); ldg_b(c + 1); }
        compute_kk(s, 1);
        if (more) sts_b(s ^ 1);
        __syncthreads();
    }

    // ---- epilogue: weighted atomic scatter ----
    const int gr = lane >> 2;
    const int gc = (lane & 3) * 2;
#pragma unroll
    for (int mt = 0; mt < 4; mt++) {
#pragma unroll
        for (int half = 0; half < 2; half++) {
            const int m = warp_m + mt * 16 + gr + half * 8;
            const int r = rs[m];
            if (r < 0) continue;
            const float w = ws[m];
            float* orow = out + (size_t)r * C_SZ;
#pragma unroll
            for (int nt = 0; nt < 8; nt++) {
                const int cc = warp_n + nt * 8 + gc;
                const int c = n0 + cc;          // even; c<C_SZ => c+1<=999
                if (c >= C_SZ) continue;
                const float v0 = acc[mt][nt][half * 2 + 0];
                const float v1 = acc[mt][nt][half * 2 + 1];
                atomicAdd(orow + c,     w * (v0 + bes[cc]));
                atomicAdd(orow + c + 1, w * (v1 + bes[cc + 1]));
            }
        }
    }
}

// ---------------- launch ----------------
extern "C" void kernel_launch(void* const* d_in, const int* in_sizes, int n_in,
                              void* d_out, int out_size) {
    const float* x  = (const float*)d_in[0];
    const float* Wr = (const float*)d_in[1];
    const float* br = (const float*)d_in[2];
    const float* We = (const float*)d_in[3];
    const float* be = (const float*)d_in[4];
    float* out = (float*)d_out;

    cudaFuncSetAttribute(expert_gemm_mma,
                         cudaFuncAttributeMaxDynamicSharedMemorySize, DYN_BYTES);

    const int n4 = (B_SZ * C_SZ) / 4;
    zero_kernel<<<(n4 + 255) / 256, 256>>>((float4*)out, n4);
    gate_fused<<<B_SZ / GR, 256>>>(x, Wr, br);
    dim3 grid((C_SZ + TN - 1) / TN, B_SZ / TM, E_SZ);
    expert_gemm_mma<<<grid, 256, DYN_BYTES>>>(x, We, be, out);
}